// round 2
// baseline (speedup 1.0000x reference)
#include <cuda_runtime.h>
#include <math.h>

// Problem constants
#define B_   2
#define LQ   1024
#define LK_  2048
#define DM   1024
#define H_   16
#define DH   64

#define OUT_ELEMS  (B_*LQ*DM)          // 2,097,152
#define ATTN_ELEMS (B_*H_*LQ*LK_)      // 67,108,864

// Scratch (allocation-free rule: __device__ globals)
__device__ float g_Q[B_*LQ*DM];        // 8 MB  projected Q, [B,Lq,D] (head-split by index)
__device__ float g_K[B_*LK_*DM];       // 16 MB projected K
__device__ float g_V[B_*LK_*DM];       // 16 MB projected V
__device__ float g_ctx[B_*LQ*DM];      // 8 MB  attention context, [B,Lq,D]

// ---------------------------------------------------------------------------
// GEMM: C[M,N] = A[M,K] @ W[N,K]^T + bias[N]   (torch Linear semantics)
// 128x128 tile, BK=16, 256 threads, 8x8 micro-tile, smem stored k-major.
// M,N,K assumed multiples of 128/128/16 (true for all calls here).
// ---------------------------------------------------------------------------
__global__ void __launch_bounds__(256) gemm_nt_bias(
    const float* __restrict__ A, const float* __restrict__ W,
    const float* __restrict__ bias, float* __restrict__ C,
    int M, int N, int K)
{
    __shared__ float As[16][132];   // [kk][m_local], pad 132 floats (528B, 16B aligned)
    __shared__ float Bs[16][132];   // [kk][n_local]

    const int t  = threadIdx.x;
    const int tx = t & 15;          // n micro index
    const int ty = t >> 4;          // m micro index
    const int m0 = blockIdx.y * 128;
    const int n0 = blockIdx.x * 128;

    const int r  = t >> 2;          // 0..63 (row within half-tile)
    const int c4 = (t & 3) << 2;    // k offset 0/4/8/12

    const float* Ap = A + (long long)(m0 + r) * K + c4;
    const float* Wp = W + (long long)(n0 + r) * K + c4;
    const long long rowOfs = (long long)64 * K;

    float acc[8][8];
#pragma unroll
    for (int i = 0; i < 8; i++)
#pragma unroll
        for (int j = 0; j < 8; j++) acc[i][j] = 0.f;

    for (int k0 = 0; k0 < K; k0 += 16) {
        float4 a0 = *(const float4*)(Ap + k0);
        float4 a1 = *(const float4*)(Ap + rowOfs + k0);
        float4 b0 = *(const float4*)(Wp + k0);
        float4 b1 = *(const float4*)(Wp + rowOfs + k0);
        __syncthreads();   // protect previous iteration's smem reads
        As[c4+0][r]    = a0.x; As[c4+1][r]    = a0.y; As[c4+2][r]    = a0.z; As[c4+3][r]    = a0.w;
        As[c4+0][r+64] = a1.x; As[c4+1][r+64] = a1.y; As[c4+2][r+64] = a1.z; As[c4+3][r+64] = a1.w;
        Bs[c4+0][r]    = b0.x; Bs[c4+1][r]    = b0.y; Bs[c4+2][r]    = b0.z; Bs[c4+3][r]    = b0.w;
        Bs[c4+0][r+64] = b1.x; Bs[c4+1][r+64] = b1.y; Bs[c4+2][r+64] = b1.z; Bs[c4+3][r+64] = b1.w;
        __syncthreads();
#pragma unroll
        for (int kk = 0; kk < 16; kk++) {
            float4 x0 = *(const float4*)&As[kk][ty*8];
            float4 x1 = *(const float4*)&As[kk][ty*8+4];
            float4 y0 = *(const float4*)&Bs[kk][tx*8];
            float4 y1 = *(const float4*)&Bs[kk][tx*8+4];
            float av[8] = {x0.x,x0.y,x0.z,x0.w,x1.x,x1.y,x1.z,x1.w};
            float bv[8] = {y0.x,y0.y,y0.z,y0.w,y1.x,y1.y,y1.z,y1.w};
#pragma unroll
            for (int i = 0; i < 8; i++)
#pragma unroll
                for (int j = 0; j < 8; j++)
                    acc[i][j] += av[i] * bv[j];
        }
    }

#pragma unroll
    for (int i = 0; i < 8; i++) {
        int m = m0 + ty*8 + i;
#pragma unroll
        for (int j = 0; j < 8; j++) {
            int n = n0 + tx*8 + j;
            C[(long long)m * N + n] = acc[i][j] + bias[n];
        }
    }
}

// ---------------------------------------------------------------------------
// Fused attention: per CTA = (q-tile of 16, head h, batch b)
//   scores = Q_h @ K_h^T / 8 + bias, mask, softmax -> attn (gmem) + sc (smem)
//   ctx    = attn @ V_h
// ---------------------------------------------------------------------------
#define TQ   16
#define KC   64
#define SPAD 65
#define ATTN_SMEM_FLOATS (TQ*LK_ + TQ*SPAD + KC*SPAD)
#define ATTN_SMEM_BYTES  (ATTN_SMEM_FLOATS * 4)

__global__ void __launch_bounds__(256) attn_kernel(
    const float* __restrict__ bias, const int* __restrict__ mask,
    float* __restrict__ attn_out)
{
    extern __shared__ float sm[];
    float* sc = sm;                       // [TQ][LK_]  scores/probs
    float* qs = sc + TQ*LK_;              // [TQ][SPAD] Q tile
    float* ks = qs + TQ*SPAD;             // [KC][SPAD] K or V chunk

    const int t  = threadIdx.x;
    const int q0 = blockIdx.x * TQ;
    const int h  = blockIdx.y;
    const int b  = blockIdx.z;

    // --- load Q tile: 16 rows x 64 floats ---
    {
        int qi = t >> 4, c = t & 15;
        float4 v = *(const float4*)&g_Q[((long long)(b*LQ + q0 + qi))*DM + h*DH + c*4];
        float* dst = &qs[qi*SPAD + c*4];
        dst[0]=v.x; dst[1]=v.y; dst[2]=v.z; dst[3]=v.w;
    }

    const int qp = t >> 5;   // 0..7  -> q pair
    const int kp = t & 31;   // 0..31 -> k pair within chunk
    const float* biasBase = bias + ((long long)((b*H_ + h)*LQ + q0)) * LK_;
    const int*   maskBase = mask + ((long long)(b*LQ + q0)) * LK_;

    // --- phase 1: scores + bias + mask ---
    for (int k0 = 0; k0 < LK_; k0 += KC) {
        __syncthreads();   // previous compute done (also covers qs store on iter 0)
        {
            int ki = t >> 2, c = t & 3;
            const float* src = &g_K[((long long)(b*LK_ + k0 + ki))*DM + h*DH];
            float* dst = &ks[ki*SPAD];
#pragma unroll
            for (int u = 0; u < 4; u++) {
                int d0 = (c + u*4) * 4;
                float4 v = *(const float4*)&src[d0];
                dst[d0]=v.x; dst[d0+1]=v.y; dst[d0+2]=v.z; dst[d0+3]=v.w;
            }
        }
        __syncthreads();

        float a00=0.f, a01=0.f, a10=0.f, a11=0.f;
        const float* q0p = &qs[(qp*2  )*SPAD];
        const float* q1p = &qs[(qp*2+1)*SPAD];
        const float* k0p = &ks[(kp*2  )*SPAD];
        const float* k1p = &ks[(kp*2+1)*SPAD];
#pragma unroll
        for (int d = 0; d < DH; d++) {
            float qa = q0p[d], qb = q1p[d];
            float ka = k0p[d], kb = k1p[d];
            a00 += qa*ka; a01 += qa*kb;
            a10 += qb*ka; a11 += qb*kb;
        }

        int qA = qp*2, qB = qA+1;
        int kA = k0 + kp*2, kB = kA+1;
        float s;
        s = a00*0.125f + biasBase[(long long)qA*LK_ + kA];
        if (maskBase[qA*LK_ + kA] == 0) s = -1e9f;
        sc[qA*LK_ + kA] = s;
        s = a01*0.125f + biasBase[(long long)qA*LK_ + kB];
        if (maskBase[qA*LK_ + kB] == 0) s = -1e9f;
        sc[qA*LK_ + kB] = s;
        s = a10*0.125f + biasBase[(long long)qB*LK_ + kA];
        if (maskBase[qB*LK_ + kA] == 0) s = -1e9f;
        sc[qB*LK_ + kA] = s;
        s = a11*0.125f + biasBase[(long long)qB*LK_ + kB];
        if (maskBase[qB*LK_ + kB] == 0) s = -1e9f;
        sc[qB*LK_ + kB] = s;
    }
    __syncthreads();

    // --- phase 2: softmax per row (16 threads per row) + write attn ---
    {
        const int row = t >> 4, g = t & 15;
        float* srow = &sc[row*LK_];

        float m = -3.4e38f;
        for (int k = g; k < LK_; k += 16) m = fmaxf(m, srow[k]);
#pragma unroll
        for (int off = 8; off; off >>= 1) m = fmaxf(m, __shfl_xor_sync(0xffffffffu, m, off, 16));

        float l = 0.f;
        for (int k = g; k < LK_; k += 16) {
            float p = __expf(fmaxf(srow[k] - m, -80.f));
            srow[k] = p;
            l += p;
        }
#pragma unroll
        for (int off = 8; off; off >>= 1) l += __shfl_xor_sync(0xffffffffu, l, off, 16);

        float inv = 1.f / l;
        float* arow = attn_out ? attn_out + ((long long)((b*H_ + h)*LQ + q0 + row)) * LK_ : (float*)0;
        for (int k = g; k < LK_; k += 16) {
            float p = srow[k] * inv;
            srow[k] = p;
            if (arow) arow[k] = p;
        }
    }

    // --- phase 3: ctx = attn @ V_h ---
    {
        const int qr = t >> 4;   // 0..15
        const int dq = t & 15;   // d = dq*4
        float c0=0.f, c1=0.f, c2=0.f, c3=0.f;
        for (int k0 = 0; k0 < LK_; k0 += KC) {
            __syncthreads();   // softmax/compute readers done before overwriting ks
            {
                int ki = t >> 2, c = t & 3;
                const float* src = &g_V[((long long)(b*LK_ + k0 + ki))*DM + h*DH];
                float* dst = &ks[ki*SPAD];
#pragma unroll
                for (int u = 0; u < 4; u++) {
                    int d0 = (c + u*4) * 4;
                    float4 v = *(const float4*)&src[d0];
                    dst[d0]=v.x; dst[d0+1]=v.y; dst[d0+2]=v.z; dst[d0+3]=v.w;
                }
            }
            __syncthreads();
            const float* srow = &sc[qr*LK_ + k0];
#pragma unroll
            for (int kk = 0; kk < KC; kk++) {
                float p = srow[kk];
                const float* v = &ks[kk*SPAD + dq*4];
                c0 += p*v[0]; c1 += p*v[1]; c2 += p*v[2]; c3 += p*v[3];
            }
        }
        float4 o; o.x=c0; o.y=c1; o.z=c2; o.w=c3;
        *(float4*)&g_ctx[((long long)(b*LQ + q0 + qr))*DM + h*DH + dq*4] = o;
    }
}

// ---------------------------------------------------------------------------
extern "C" void kernel_launch(void* const* d_in, const int* in_sizes, int n_in,
                              void* d_out, int out_size)
{
    const float* query = (const float*)d_in[0];
    const float* key   = (const float*)d_in[1];
    const float* value = (const float*)d_in[2];
    const int*   mask  = (const int*)  d_in[3];
    const float* abias = (const float*)d_in[4];
    const float* Wq = (const float*)d_in[5];
    const float* bq = (const float*)d_in[6];
    const float* Wk = (const float*)d_in[7];
    const float* bk = (const float*)d_in[8];
    const float* Wv = (const float*)d_in[9];
    const float* bv = (const float*)d_in[10];
    const float* Wo = (const float*)d_in[11];
    const float* bo = (const float*)d_in[12];
    float* out = (float*)d_out;

    float *gQ, *gK, *gV, *gC;
    cudaGetSymbolAddress((void**)&gQ, g_Q);
    cudaGetSymbolAddress((void**)&gK, g_K);
    cudaGetSymbolAddress((void**)&gV, g_V);
    cudaGetSymbolAddress((void**)&gC, g_ctx);

    // attn goes after out if the harness compares the full tuple
    float* attn_ptr = (out_size >= OUT_ELEMS + ATTN_ELEMS) ? out + OUT_ELEMS : (float*)0;

    static int attr_done = 0;
    (void)attr_done; // attribute set every call; deterministic & capture-safe
    cudaFuncSetAttribute(attn_kernel, cudaFuncAttributeMaxDynamicSharedMemorySize,
                         ATTN_SMEM_BYTES);

    // Projections
    gemm_nt_bias<<<dim3(DM/128, (B_*LQ)/128), 256>>>(query, Wq, bq, gQ, B_*LQ,  DM, DM);
    gemm_nt_bias<<<dim3(DM/128, (B_*LK_)/128), 256>>>(key,   Wk, bk, gK, B_*LK_, DM, DM);
    gemm_nt_bias<<<dim3(DM/128, (B_*LK_)/128), 256>>>(value, Wv, bv, gV, B_*LK_, DM, DM);

    // Attention (scores + softmax + attn output + context)
    attn_kernel<<<dim3(LQ/TQ, H_, B_), 256, ATTN_SMEM_BYTES>>>(abias, mask, attn_ptr);

    // Output projection
    gemm_nt_bias<<<dim3(DM/128, (B_*LQ)/128), 256>>>(gC, Wo, bo, out, B_*LQ, DM, DM);
}

// round 4
// speedup vs baseline: 3.3319x; 3.3319x over previous
#include <cuda_runtime.h>
#include <cuda_bf16.h>
#include <cstdint>

#define B_  2
#define LQ  1024
#define LK  2048
#define DM  1024
#define NH  16
#define DH  64
#define BH  (B_*NH)
#define OUT_ELEMS (B_*LQ*DM)

// bf16 hi/lo pools for converted inputs + ctx (elements)
#define P_QUERY 0
#define P_KEY   (2*1024*1024)
#define P_VALUE (6*1024*1024)
#define P_WQ    (10*1024*1024)
#define P_WK    (11*1024*1024)
#define P_WV    (12*1024*1024)
#define P_WO    (13*1024*1024)
#define P_CTX   (14*1024*1024)
#define P_TOTAL (16*1024*1024)

__device__ __align__(256) __nv_bfloat16 g_hi[P_TOTAL];
__device__ __align__(256) __nv_bfloat16 g_lo[P_TOTAL];
__device__ __align__(256) __nv_bfloat16 g_Qhi[BH*LQ*DH];
__device__ __align__(256) __nv_bfloat16 g_Qlo[BH*LQ*DH];
__device__ __align__(256) __nv_bfloat16 g_Khi[BH*LK*DH];
__device__ __align__(256) __nv_bfloat16 g_Klo[BH*LK*DH];
__device__ __align__(256) __nv_bfloat16 g_Vthi[BH*DH*LK];   // [bh, d, t]
__device__ __align__(256) __nv_bfloat16 g_Vtlo[BH*DH*LK];

// ---------------- low-level helpers ----------------------------------------
__device__ __forceinline__ uint32_t smem_u32(const void* p){
    uint32_t a;
    asm("{ .reg .u64 t; cvta.to.shared.u64 t, %1; cvt.u32.u64 %0, t; }" : "=r"(a) : "l"(p));
    return a;
}
#define CP16(d,s) asm volatile("cp.async.cg.shared.global [%0], [%1], 16;" :: "r"(d), "l"(__cvta_generic_to_global(s)))
#define CPCOMMIT() asm volatile("cp.async.commit_group;" ::: "memory")
#define CPWAIT(n)  asm volatile("cp.async.wait_group %0;" :: "n"(n) : "memory")

__device__ __forceinline__ void ldm_x4(uint32_t* r, uint32_t a){
    asm volatile("ldmatrix.sync.aligned.m8n8.x4.shared.b16 {%0,%1,%2,%3}, [%4];"
        : "=r"(r[0]),"=r"(r[1]),"=r"(r[2]),"=r"(r[3]) : "r"(a));
}
__device__ __forceinline__ void ldm_x2(uint32_t* r, uint32_t a){
    asm volatile("ldmatrix.sync.aligned.m8n8.x2.shared.b16 {%0,%1}, [%2];"
        : "=r"(r[0]),"=r"(r[1]) : "r"(a));
}
__device__ __forceinline__ void mma16816(float* d, const uint32_t* a, const uint32_t* b){
    asm volatile("mma.sync.aligned.m16n8k16.row.col.f32.bf16.bf16.f32 "
        "{%0,%1,%2,%3}, {%4,%5,%6,%7}, {%8,%9}, {%0,%1,%2,%3};"
        : "+f"(d[0]),"+f"(d[1]),"+f"(d[2]),"+f"(d[3])
        : "r"(a[0]),"r"(a[1]),"r"(a[2]),"r"(a[3]), "r"(b[0]),"r"(b[1]));
}
__device__ __forceinline__ void fsplit(float x, __nv_bfloat16& h, __nv_bfloat16& l){
    h = __float2bfloat16(x);
    l = __float2bfloat16(x - __bfloat162float(h));
}
__device__ __forceinline__ uint32_t pack2(__nv_bfloat16 a, __nv_bfloat16 b){
    return (uint32_t)__bfloat16_as_ushort(a) | ((uint32_t)__bfloat16_as_ushort(b) << 16);
}

// ---------------- input conversion fp32 -> bf16 hi/lo -----------------------
__global__ void __launch_bounds__(256) cvt_kernel(const float4* __restrict__ src,
                                                  uint2* __restrict__ hi,
                                                  uint2* __restrict__ lo, int n4)
{
    int i = blockIdx.x*256 + threadIdx.x;
    if (i >= n4) return;
    float4 v = src[i];
    __nv_bfloat16 h0,l0,h1,l1,h2,l2,h3,l3;
    fsplit(v.x,h0,l0); fsplit(v.y,h1,l1); fsplit(v.z,h2,l2); fsplit(v.w,h3,l3);
    hi[i] = make_uint2(pack2(h0,h1), pack2(h2,h3));
    lo[i] = make_uint2(pack2(l0,l1), pack2(l2,l3));
}

// ============================================================================
// Projection GEMM: C[128m x 128n] = A[M,1024] @ W[128,1024]^T + bias
// A,W pre-converted bf16 hi/lo. 8 warps (4m x 2n), warp tile 32x64.
// smem: [0,512) bias | [512, +2*73728) 2-stage {Ah,Al,Wh,Wl} 128x72 bf16 tiles
//       stage fp32 128x132 at 147968. Total 215552 B.
// MODE 0: Q (scale 1/8, bf16 hi/lo head-split), 1: K, 2: V (transposed), 3: O fp32
// ============================================================================
#define TSTRIDE 144            // bytes per smem tile row (72 bf16)
#define TILESZ  18432          // 128*144
#define PROJ_SMEM (512 + 2*4*TILESZ + 128*132*4)

template<int MODE>
__global__ void __launch_bounds__(256) proj_kernel(
    const __nv_bfloat16* __restrict__ Ah_g, const __nv_bfloat16* __restrict__ Al_g,
    const __nv_bfloat16* __restrict__ Wh_g, const __nv_bfloat16* __restrict__ Wl_g,
    const float* __restrict__ bias, float* __restrict__ outp, int Ltok)
{
    extern __shared__ char smc[];
    const uint32_t sb = smem_u32(smc);
    const uint32_t tbase = sb + 512;
    float* bias_sm = (float*)smc;
    float* stg = (float*)(smc + 512 + 2*4*TILESZ);

    const int tid = threadIdx.x, lane = tid&31, wid = tid>>5;
    const int wm = wid>>1, wn = wid&1;
    const int m0 = blockIdx.y*128, n0 = blockIdx.x*128;

    if (tid < 128) bias_sm[tid] = bias[n0+tid];

    const __nv_bfloat16* gp[4] = {
        Ah_g + (size_t)m0*DM, Al_g + (size_t)m0*DM,
        Wh_g + (size_t)n0*DM, Wl_g + (size_t)n0*DM };

    float acc[2][8][4];
#pragma unroll
    for (int a=0;a<2;a++)
#pragma unroll
        for (int b=0;b<8;b++)
#pragma unroll
            for (int c=0;c<4;c++) acc[a][b][c]=0.f;

    const uint32_t aoff = (uint32_t)((wm*32 + (lane&15))*TSTRIDE + (lane>>4)*16);
    const uint32_t boff = (uint32_t)((wn*64 + (lane&7))*TSTRIDE + ((lane>>3)&1)*16);

    // prefetch chunk 0
#pragma unroll
    for (int t4=0;t4<4;t4++)
#pragma unroll
        for (int i=0;i<4;i++){
            int idx = tid + i*256, row = idx>>3, c = idx&7;
            CP16(tbase + t4*TILESZ + row*TSTRIDE + c*16, gp[t4] + (size_t)row*DM + c*8);
        }
    CPCOMMIT();

    for (int ck=0; ck<16; ck++){
        if (ck+1 < 16){
            uint32_t st1 = tbase + ((ck+1)&1)*(4*TILESZ);
#pragma unroll
            for (int t4=0;t4<4;t4++)
#pragma unroll
                for (int i=0;i<4;i++){
                    int idx = tid + i*256, row = idx>>3, c = idx&7;
                    CP16(st1 + t4*TILESZ + row*TSTRIDE + c*16,
                         gp[t4] + (size_t)row*DM + (ck+1)*64 + c*8);
                }
            CPCOMMIT();
            CPWAIT(1);
        } else {
            CPWAIT(0);
        }
        __syncthreads();

        const uint32_t TA  = tbase + (ck&1)*(4*TILESZ);
        const uint32_t TAl = TA + TILESZ, TW = TA + 2*TILESZ, TWl = TA + 3*TILESZ;
#pragma unroll
        for (int ks=0;ks<4;ks++){
            uint32_t ah[2][4], al[2][4];
            ldm_x4(ah[0], TA  + aoff + ks*32);
            ldm_x4(ah[1], TA  + aoff + 16*TSTRIDE + ks*32);
            ldm_x4(al[0], TAl + aoff + ks*32);
            ldm_x4(al[1], TAl + aoff + 16*TSTRIDE + ks*32);
#pragma unroll
            for (int nt=0;nt<8;nt++){
                uint32_t bh[2], bl[2];
                ldm_x2(bh, TW  + boff + nt*8*TSTRIDE + ks*32);
                ldm_x2(bl, TWl + boff + nt*8*TSTRIDE + ks*32);
#pragma unroll
                for (int mt=0;mt<2;mt++){
                    mma16816(acc[mt][nt], ah[mt], bh);
                    mma16816(acc[mt][nt], ah[mt], bl);
                    mma16816(acc[mt][nt], al[mt], bh);
                }
            }
        }
        __syncthreads();
    }

    // stage accumulators (+bias, Q-scale) to fp32 smem
    {
        const int g = lane>>2, tg = lane&3;
#pragma unroll
        for (int mt=0;mt<2;mt++)
#pragma unroll
            for (int nt=0;nt<8;nt++){
                int row = wm*32 + mt*16 + g;
                int col = wn*64 + nt*8 + tg*2;
                float b0 = bias_sm[col], b1 = bias_sm[col+1];
                float v0 = acc[mt][nt][0]+b0, v1 = acc[mt][nt][1]+b1;
                float v2 = acc[mt][nt][2]+b0, v3 = acc[mt][nt][3]+b1;
                if (MODE==0){ v0*=0.125f; v1*=0.125f; v2*=0.125f; v3*=0.125f; }
                stg[row*132+col] = v0;  stg[row*132+col+1] = v1;
                stg[(row+8)*132+col] = v2; stg[(row+8)*132+col+1] = v3;
            }
    }
    __syncthreads();

    if (MODE==3){
        const int r2 = tid>>1, hf = tid&1;
        const float* srow = stg + r2*132 + hf*64;
        float* drow = outp + (size_t)(m0+r2)*DM + n0 + hf*64;
#pragma unroll
        for (int j=0;j<16;j++) *(float4*)(drow + j*4) = *(const float4*)(srow + j*4);
    } else if (MODE<2){
        const int r2 = tid>>1, hf = tid&1;
        const int rowg = m0 + r2;
        const int b = rowg / Ltok, tok = rowg - b*Ltok;
        const int h = (n0>>6) + hf;
        const float* srow = stg + r2*132 + hf*64;
        __nv_bfloat16* gh = ((MODE==0)? g_Qhi : g_Khi) + ((size_t)(b*NH+h)*Ltok + tok)*DH;
        __nv_bfloat16* gl = ((MODE==0)? g_Qlo : g_Klo) + ((size_t)(b*NH+h)*Ltok + tok)*DH;
#pragma unroll
        for (int j=0;j<8;j++){
            __nv_bfloat16 h0,l0,h1,l1,h2,l2,h3,l3,h4,l4,h5,l5,h6,l6,h7,l7;
            fsplit(srow[j*8+0],h0,l0); fsplit(srow[j*8+1],h1,l1);
            fsplit(srow[j*8+2],h2,l2); fsplit(srow[j*8+3],h3,l3);
            fsplit(srow[j*8+4],h4,l4); fsplit(srow[j*8+5],h5,l5);
            fsplit(srow[j*8+6],h6,l6); fsplit(srow[j*8+7],h7,l7);
            ((uint4*)gh)[j] = make_uint4(pack2(h0,h1),pack2(h2,h3),pack2(h4,h5),pack2(h6,h7));
            ((uint4*)gl)[j] = make_uint4(pack2(l0,l1),pack2(l2,l3),pack2(l4,l5),pack2(l6,l7));
        }
    } else { // MODE 2: V transposed store [bh, d, t]
        const int dl = tid>>1, th = tid&1;
        const int dg = n0 + dl, h = dg>>6, dd = dg&63;
        const int b = m0 / Ltok, toff = m0 - b*Ltok;
        __nv_bfloat16* vh = g_Vthi + ((size_t)(b*NH+h)*DH + dd)*LK + toff + th*64;
        __nv_bfloat16* vl = g_Vtlo + ((size_t)(b*NH+h)*DH + dd)*LK + toff + th*64;
#pragma unroll
        for (int j=0;j<16;j++){
            int t4 = th*64 + j*4;
            __nv_bfloat16 h0,l0,h1,l1,h2,l2,h3,l3;
            fsplit(stg[(t4+0)*132+dl],h0,l0);
            fsplit(stg[(t4+1)*132+dl],h1,l1);
            fsplit(stg[(t4+2)*132+dl],h2,l2);
            fsplit(stg[(t4+3)*132+dl],h3,l3);
            ((uint2*)vh)[j] = make_uint2(pack2(h0,h1), pack2(h2,h3));
            ((uint2*)vl)[j] = make_uint2(pack2(l0,l1), pack2(l2,l3));
        }
    }
}

// ============================================================================
// Scores: S[q0:128, k0:128] = Q@K^T (Q pre-scaled) + bias, mask -> attn raw
// smem: tiles {Qh,Ql,Kh,Kl} @0 (73728) | stage fp32 128x132 @73728. 141312 B.
// ============================================================================
#define SC_SMEM (4*TILESZ + 128*132*4)
__global__ void __launch_bounds__(256) scores_kernel(
    const float* __restrict__ bias, const int* __restrict__ mask,
    float* __restrict__ attn)
{
    extern __shared__ char smc[];
    const uint32_t sb = smem_u32(smc);
    float* stg = (float*)(smc + 4*TILESZ);
    const int tid = threadIdx.x, lane = tid&31, wid = tid>>5;
    const int wm = wid>>1, wn = wid&1;
    const int k0 = blockIdx.x*128, q0 = blockIdx.y*128, bh = blockIdx.z, b = bh>>4;

    const __nv_bfloat16* gp[4] = {
        g_Qhi + ((size_t)bh*LQ + q0)*DH, g_Qlo + ((size_t)bh*LQ + q0)*DH,
        g_Khi + ((size_t)bh*LK + k0)*DH, g_Klo + ((size_t)bh*LK + k0)*DH };
#pragma unroll
    for (int t4=0;t4<4;t4++)
#pragma unroll
        for (int i=0;i<4;i++){
            int idx = tid + i*256, row = idx>>3, c = idx&7;
            CP16(sb + t4*TILESZ + row*TSTRIDE + c*16, gp[t4] + (size_t)row*DH + c*8);
        }
    CPCOMMIT(); CPWAIT(0);
    __syncthreads();

    float acc[2][8][4];
#pragma unroll
    for (int a=0;a<2;a++)
#pragma unroll
        for (int c=0;c<8;c++)
#pragma unroll
            for (int d=0;d<4;d++) acc[a][c][d]=0.f;

    const uint32_t aoff = (uint32_t)((wm*32 + (lane&15))*TSTRIDE + (lane>>4)*16);
    const uint32_t boff = (uint32_t)((wn*64 + (lane&7))*TSTRIDE + ((lane>>3)&1)*16);
    const uint32_t TQh = sb, TQl = sb+TILESZ, TKh = sb+2*TILESZ, TKl = sb+3*TILESZ;
#pragma unroll
    for (int ks=0;ks<4;ks++){
        uint32_t ah[2][4], al[2][4];
        ldm_x4(ah[0], TQh + aoff + ks*32);
        ldm_x4(ah[1], TQh + aoff + 16*TSTRIDE + ks*32);
        ldm_x4(al[0], TQl + aoff + ks*32);
        ldm_x4(al[1], TQl + aoff + 16*TSTRIDE + ks*32);
#pragma unroll
        for (int nt=0;nt<8;nt++){
            uint32_t bh2[2], bl2[2];
            ldm_x2(bh2, TKh + boff + nt*8*TSTRIDE + ks*32);
            ldm_x2(bl2, TKl + boff + nt*8*TSTRIDE + ks*32);
#pragma unroll
            for (int mt=0;mt<2;mt++){
                mma16816(acc[mt][nt], ah[mt], bh2);
                mma16816(acc[mt][nt], ah[mt], bl2);
                mma16816(acc[mt][nt], al[mt], bh2);
            }
        }
    }
    __syncthreads();  // tiles no longer needed; stage region is separate anyway
    {
        const int g = lane>>2, tg = lane&3;
#pragma unroll
        for (int mt=0;mt<2;mt++)
#pragma unroll
            for (int nt=0;nt<8;nt++){
                int row = wm*32 + mt*16 + g;
                int col = wn*64 + nt*8 + tg*2;
                stg[row*132+col] = acc[mt][nt][0];  stg[row*132+col+1] = acc[mt][nt][1];
                stg[(row+8)*132+col] = acc[mt][nt][2]; stg[(row+8)*132+col+1] = acc[mt][nt][3];
            }
    }
    __syncthreads();
    {
        const int r2 = tid>>1, hf = tid&1;
        const int q = q0 + r2;
        const float* srow = stg + r2*132 + hf*64;
        const float* brow = bias + ((size_t)bh*LQ + q)*LK + k0 + hf*64;
        const int*   mrow = mask + ((size_t)b*LQ + q)*LK + k0 + hf*64;
        float*       arow = attn + ((size_t)bh*LQ + q)*LK + k0 + hf*64;
#pragma unroll
        for (int j=0;j<16;j++){
            float4 s = *(const float4*)(srow + j*4);
            float4 bb = *(const float4*)(brow + j*4);
            int4   mm = *(const int4*)  (mrow + j*4);
            s.x = mm.x ? s.x+bb.x : -1e9f;
            s.y = mm.y ? s.y+bb.y : -1e9f;
            s.z = mm.z ? s.z+bb.z : -1e9f;
            s.w = mm.w ? s.w+bb.w : -1e9f;
            *(float4*)(arow + j*4) = s;
        }
    }
}

// ============================================================================
// Row softmax in place: 1 warp per row of 2048
// ============================================================================
__global__ void __launch_bounds__(256) softmax_kernel(float* __restrict__ attn)
{
    const int wid = threadIdx.x>>5, lane = threadIdx.x&31;
    float* p = attn + ((size_t)blockIdx.x*8 + wid)*LK;
    float v[64];
#pragma unroll
    for (int i=0;i<16;i++){
        float4 t = *(const float4*)(p + (i*32+lane)*4);
        v[i*4]=t.x; v[i*4+1]=t.y; v[i*4+2]=t.z; v[i*4+3]=t.w;
    }
    float m = v[0];
#pragma unroll
    for (int i=1;i<64;i++) m = fmaxf(m, v[i]);
#pragma unroll
    for (int o=16;o;o>>=1) m = fmaxf(m, __shfl_xor_sync(0xffffffffu, m, o));
    float s = 0.f;
#pragma unroll
    for (int i=0;i<64;i++){ v[i] = __expf(v[i]-m); s += v[i]; }
#pragma unroll
    for (int o=16;o;o>>=1) s += __shfl_xor_sync(0xffffffffu, s, o);
    const float inv = 1.f/s;
#pragma unroll
    for (int i=0;i<16;i++){
        float4 t;
        t.x=v[i*4]*inv; t.y=v[i*4+1]*inv; t.z=v[i*4+2]*inv; t.w=v[i*4+3]*inv;
        *(float4*)(p + (i*32+lane)*4) = t;
    }
}

// ============================================================================
// PV: ctx[q0:128, h*64:+64] = P @ Vt^T ; P fp32->hi/lo on load, 32 chunks of 64
// smem: Ph@0, Pl@18432 (128x72), Vh@36864, Vl@46080 (64x72), stage @55296. 90112 B
// ============================================================================
#define PV_SMEM (2*TILESZ + 2*9216 + 128*68*4)
__global__ void __launch_bounds__(256) pv_kernel(const float* __restrict__ attn)
{
    extern __shared__ char smc[];
    const uint32_t sb = smem_u32(smc);
    float* stg = (float*)(smc + 2*TILESZ + 2*9216);
    const int tid = threadIdx.x, lane = tid&31, wid = tid>>5;
    const int wm = wid>>1, wn = wid&1;
    const int q0 = blockIdx.x*128, bh = blockIdx.y, b = bh>>4, h = bh&15;

    const uint32_t TPh = sb, TPl = sb+TILESZ, TVh = sb+2*TILESZ, TVl = TVh+9216;
    const float* Pg = attn + ((size_t)bh*LQ + q0)*LK;
    const __nv_bfloat16* Vhg = g_Vthi + (size_t)bh*DH*LK;
    const __nv_bfloat16* Vlg = g_Vtlo + (size_t)bh*DH*LK;

    float acc[2][4][4];
#pragma unroll
    for (int a=0;a<2;a++)
#pragma unroll
        for (int c=0;c<4;c++)
#pragma unroll
            for (int d=0;d<4;d++) acc[a][c][d]=0.f;

    const uint32_t aoff = (uint32_t)((wm*32 + (lane&15))*TSTRIDE + (lane>>4)*16);
    const uint32_t boff = (uint32_t)((wn*32 + (lane&7))*TSTRIDE + ((lane>>3)&1)*16);

    for (int ck=0; ck<32; ck++){
        const int t0 = ck*64;
        __syncthreads();
        // convert P chunk fp32 -> hi/lo bf16 smem
#pragma unroll
        for (int i=0;i<8;i++){
            int idx = tid + i*256, row = idx>>4, c4 = idx&15;
            float4 v = *(const float4*)(Pg + (size_t)row*LK + t0 + c4*4);
            __nv_bfloat16 h0,l0,h1,l1,h2,l2,h3,l3;
            fsplit(v.x,h0,l0); fsplit(v.y,h1,l1); fsplit(v.z,h2,l2); fsplit(v.w,h3,l3);
            *(uint2*)(smc + (row*TSTRIDE + c4*8))          = make_uint2(pack2(h0,h1),pack2(h2,h3));
            *(uint2*)(smc + TILESZ + (row*TSTRIDE + c4*8)) = make_uint2(pack2(l0,l1),pack2(l2,l3));
        }
        // V tiles via cp.async
#pragma unroll
        for (int i=0;i<2;i++){
            int idx = tid + i*256, row = idx>>3, c = idx&7;
            CP16(TVh + row*TSTRIDE + c*16, Vhg + (size_t)row*LK + t0 + c*8);
            CP16(TVl + row*TSTRIDE + c*16, Vlg + (size_t)row*LK + t0 + c*8);
        }
        CPCOMMIT(); CPWAIT(0);
        __syncthreads();
#pragma unroll
        for (int ks=0;ks<4;ks++){
            uint32_t ah[2][4], al[2][4];
            ldm_x4(ah[0], TPh + aoff + ks*32);
            ldm_x4(ah[1], TPh + aoff + 16*TSTRIDE + ks*32);
            ldm_x4(al[0], TPl + aoff + ks*32);
            ldm_x4(al[1], TPl + aoff + 16*TSTRIDE + ks*32);
#pragma unroll
            for (int nt=0;nt<4;nt++){
                uint32_t bh2[2], bl2[2];
                ldm_x2(bh2, TVh + boff + nt*8*TSTRIDE + ks*32);
                ldm_x2(bl2, TVl + boff + nt*8*TSTRIDE + ks*32);
#pragma unroll
                for (int mt=0;mt<2;mt++){
                    mma16816(acc[mt][nt], ah[mt], bh2);
                    mma16816(acc[mt][nt], ah[mt], bl2);
                    mma16816(acc[mt][nt], al[mt], bh2);
                }
            }
        }
    }
    __syncthreads();
    {
        const int g = lane>>2, tg = lane&3;
#pragma unroll
        for (int mt=0;mt<2;mt++)
#pragma unroll
            for (int nt=0;nt<4;nt++){
                int row = wm*32 + mt*16 + g;
                int col = wn*32 + nt*8 + tg*2;
                stg[row*68+col] = acc[mt][nt][0];  stg[row*68+col+1] = acc[mt][nt][1];
                stg[(row+8)*68+col] = acc[mt][nt][2]; stg[(row+8)*68+col+1] = acc[mt][nt][3];
            }
    }
    __syncthreads();
    {
        const int r2 = tid>>1, hf = tid&1;
        const float* srow = stg + r2*68 + hf*32;
        size_t base = ((size_t)(b*LQ + q0 + r2))*DM + h*DH + hf*32;
        __nv_bfloat16* ch = g_hi + P_CTX + base;
        __nv_bfloat16* cl = g_lo + P_CTX + base;
#pragma unroll
        for (int j=0;j<4;j++){
            __nv_bfloat16 h0,l0,h1,l1,h2,l2,h3,l3,h4,l4,h5,l5,h6,l6,h7,l7;
            fsplit(srow[j*8+0],h0,l0); fsplit(srow[j*8+1],h1,l1);
            fsplit(srow[j*8+2],h2,l2); fsplit(srow[j*8+3],h3,l3);
            fsplit(srow[j*8+4],h4,l4); fsplit(srow[j*8+5],h5,l5);
            fsplit(srow[j*8+6],h6,l6); fsplit(srow[j*8+7],h7,l7);
            ((uint4*)ch)[j] = make_uint4(pack2(h0,h1),pack2(h2,h3),pack2(h4,h5),pack2(h6,h7));
            ((uint4*)cl)[j] = make_uint4(pack2(l0,l1),pack2(l2,l3),pack2(l4,l5),pack2(l6,l7));
        }
    }
}

// ============================================================================
extern "C" void kernel_launch(void* const* d_in, const int* in_sizes, int n_in,
                              void* d_out, int out_size)
{
    const float* query = (const float*)d_in[0];
    const float* key   = (const float*)d_in[1];
    const float* value = (const float*)d_in[2];
    const int*   mask  = (const int*)  d_in[3];
    const float* abias = (const float*)d_in[4];
    const float* Wq = (const float*)d_in[5];
    const float* bq = (const float*)d_in[6];
    const float* Wk = (const float*)d_in[7];
    const float* bk = (const float*)d_in[8];
    const float* Wv = (const float*)d_in[9];
    const float* bv = (const float*)d_in[10];
    const float* Wo = (const float*)d_in[11];
    const float* bo = (const float*)d_in[12];
    float* out  = (float*)d_out;
    float* attn = out + OUT_ELEMS;

    __nv_bfloat16 *hi, *lo;
    cudaGetSymbolAddress((void**)&hi, g_hi);
    cudaGetSymbolAddress((void**)&lo, g_lo);

    cudaFuncSetAttribute(proj_kernel<0>, cudaFuncAttributeMaxDynamicSharedMemorySize, PROJ_SMEM);
    cudaFuncSetAttribute(proj_kernel<1>, cudaFuncAttributeMaxDynamicSharedMemorySize, PROJ_SMEM);
    cudaFuncSetAttribute(proj_kernel<2>, cudaFuncAttributeMaxDynamicSharedMemorySize, PROJ_SMEM);
    cudaFuncSetAttribute(proj_kernel<3>, cudaFuncAttributeMaxDynamicSharedMemorySize, PROJ_SMEM);
    cudaFuncSetAttribute(scores_kernel,  cudaFuncAttributeMaxDynamicSharedMemorySize, SC_SMEM);
    cudaFuncSetAttribute(pv_kernel,      cudaFuncAttributeMaxDynamicSharedMemorySize, PV_SMEM);

    // convert inputs to bf16 hi/lo
    struct { const float* s; int off; int n; } cv[7] = {
        {query, P_QUERY, B_*LQ*DM}, {key, P_KEY, B_*LK*DM}, {value, P_VALUE, B_*LK*DM},
        {Wq, P_WQ, DM*DM}, {Wk, P_WK, DM*DM}, {Wv, P_WV, DM*DM}, {Wo, P_WO, DM*DM}};
    for (int i=0;i<7;i++){
        int n4 = cv[i].n/4;
        cvt_kernel<<<(n4+255)/256, 256>>>((const float4*)cv[i].s,
            (uint2*)(hi+cv[i].off), (uint2*)(lo+cv[i].off), n4);
    }

    proj_kernel<0><<<dim3(8,16), 256, PROJ_SMEM>>>(hi+P_QUERY, lo+P_QUERY, hi+P_WQ, lo+P_WQ, bq, nullptr, LQ);
    proj_kernel<1><<<dim3(8,32), 256, PROJ_SMEM>>>(hi+P_KEY,   lo+P_KEY,   hi+P_WK, lo+P_WK, bk, nullptr, LK);
    proj_kernel<2><<<dim3(8,32), 256, PROJ_SMEM>>>(hi+P_VALUE, lo+P_VALUE, hi+P_WV, lo+P_WV, bv, nullptr, LK);

    scores_kernel<<<dim3(LK/128, LQ/128, BH), 256, SC_SMEM>>>(abias, mask, attn);
    softmax_kernel<<<(BH*LQ)/8, 256>>>(attn);
    pv_kernel<<<dim3(LQ/128, BH), 256, PV_SMEM>>>(attn);

    proj_kernel<3><<<dim3(8,16), 256, PROJ_SMEM>>>(hi+P_CTX, lo+P_CTX, hi+P_WO, lo+P_WO, bo, out, LQ);
}